// round 1
// baseline (speedup 1.0000x reference)
#include <cuda_runtime.h>

#define NN    5000
#define NE    160000
#define HID   64
#define NPAD  5120      // padded node stride for transposed h_part
#define BATCH 512
#define NPB   8         // nodes per block in node2 kernels

// ---------------- scratch (device globals: allocation-free) ----------------
__device__ float g_msg1[NN * 4];
__device__ float g_deg [NN];
__device__ float g_h1  [NN * HID];
__device__ float g_msg2[NN * HID];
__device__ float g_h2  [NN * HID];
__device__ float g_hpT [HID * NPAD];   // h_part transposed [h][n]; pad region stays 0
__device__ float g_tp  [BATCH * HID];
__device__ int   g_i32;                // 1 if edge_index buffer is int32

// ---------------- zero accumulators (must run every call) ----------------
__global__ void k_zero() {
    int i = blockIdx.x * blockDim.x + threadIdx.x;
    if (i == 0) g_i32 = 0;
    if (i < NN * 4) g_msg1[i] = 0.f;
    if (i < NN)     g_deg[i]  = 0.f;
    for (int j = i; j < NN * HID; j += gridDim.x * blockDim.x) g_msg2[j] = 0.f;
}

// ---------------- detect int32 vs int64 edge_index ----------------
// Guaranteed-safe window: 320000 u32 words (the int32 size). If data is int64,
// every odd u32 word is a high half of a value in [0,5000) -> 0. If int32, odd
// words are random node ids, almost surely nonzero somewhere.
__global__ void k_detect(const unsigned int* __restrict__ w) {
    unsigned int acc = 0;
    for (int i = blockIdx.x * blockDim.x + threadIdx.x; i < NE; i += gridDim.x * blockDim.x)
        acc |= w[2 * i + 1];
    if (__any_sync(0xffffffffu, acc != 0) && (threadIdx.x & 31) == 0)
        atomicOr(&g_i32, 1);
}

// ---------------- layer-1 scatter: msg_sum over 4 features + degree ----------------
__global__ void k_scatter1(const void* __restrict__ ei, const float* __restrict__ x) {
    int e = blockIdx.x * blockDim.x + threadIdx.x;
    if (e >= NE) return;
    int s, d;
    if (g_i32) {
        const int* p = (const int*)ei;
        s = p[e]; d = p[NE + e];
    } else {
        const long long* p = (const long long*)ei;
        s = (int)p[e]; d = (int)p[NE + e];
    }
    float4 xv = *(const float4*)(x + (size_t)s * 4);
    atomicAdd(&g_msg1[d * 4 + 0], xv.x);
    atomicAdd(&g_msg1[d * 4 + 1], xv.y);
    atomicAdd(&g_msg1[d * 4 + 2], xv.z);
    atomicAdd(&g_msg1[d * 4 + 3], xv.w);
    atomicAdd(&g_deg[d], 1.f);
}

// ---------------- layer-1 node update: h1 = relu(Wl1@mean + bl1 + Wr1@x) ----------------
__global__ void k_node1(const float* __restrict__ x,
                        const float* __restrict__ Wl1, const float* __restrict__ bl1,
                        const float* __restrict__ Wr1) {
    int t = blockIdx.x * blockDim.x + threadIdx.x;
    if (t >= NN * HID) return;
    int n = t >> 6, o = t & 63;
    float invd = 1.f / fmaxf(g_deg[n], 1.f);
    float acc = bl1[o];
#pragma unroll
    for (int f = 0; f < 4; f++)
        acc += Wl1[o * 4 + f] * (g_msg1[n * 4 + f] * invd) + Wr1[o * 4 + f] * x[n * 4 + f];
    g_h1[t] = fmaxf(acc, 0.f);
}

// ---------------- layer-2 scatter: msg2[dst] += h1[src] (warp per edge) ----------------
__global__ void k_scatter2(const void* __restrict__ ei) {
    long long t = (long long)blockIdx.x * blockDim.x + threadIdx.x;
    int e = (int)(t >> 5);
    int lane = threadIdx.x & 31;
    if (e >= NE) return;
    int s = 0, d = 0;
    if (lane == 0) {
        if (g_i32) {
            const int* p = (const int*)ei;
            s = p[e]; d = p[NE + e];
        } else {
            const long long* p = (const long long*)ei;
            s = (int)p[e]; d = (int)p[NE + e];
        }
    }
    s = __shfl_sync(0xffffffffu, s, 0);
    d = __shfl_sync(0xffffffffu, d, 0);
    float v0 = g_h1[s * 64 + lane];
    float v1 = g_h1[s * 64 + 32 + lane];
    atomicAdd(&g_msg2[d * 64 + lane],      v0);
    atomicAdd(&g_msg2[d * 64 + 32 + lane], v1);
}

// ---------------- layer-2 node update: h2 = relu(Wl2@mean2 + bl2 + Wr2@h1) ----------------
__global__ void k_node2a(const float* __restrict__ Wl2, const float* __restrict__ bl2,
                         const float* __restrict__ Wr2) {
    __shared__ float sWl[64 * 65], sWr[64 * 65];   // transposed [h][o], padded
    __shared__ float s_mean[64], s_x[64];
    int o = threadIdx.x;
    for (int idx = o; idx < 4096; idx += 64) {
        int r = idx >> 6, c = idx & 63;            // r = out, c = in
        sWl[c * 65 + r] = Wl2[idx];
        sWr[c * 65 + r] = Wr2[idx];
    }
    float bias = bl2[o];
    __syncthreads();
    int n0 = blockIdx.x * NPB;
    for (int ni = 0; ni < NPB; ni++) {
        int n = n0 + ni;
        if (n >= NN) break;                        // uniform across block
        float invd = 1.f / fmaxf(g_deg[n], 1.f);
        s_mean[o] = g_msg2[n * 64 + o] * invd;
        s_x[o]    = g_h1[n * 64 + o];
        __syncthreads();
        float acc = bias;
#pragma unroll
        for (int h = 0; h < 64; h++)
            acc += sWl[h * 65 + o] * s_mean[h] + sWr[h * 65 + o] * s_x[h];
        g_h2[n * 64 + o] = fmaxf(acc, 0.f);
        __syncthreads();
    }
}

// ---------------- h_part = h2 @ Wc1[:, :64]^T, stored transposed ----------------
__global__ void k_node2b(const float* __restrict__ Wc1) {
    __shared__ float sW[64 * 65];   // transposed [h][o]
    __shared__ float s_h[64];
    int o = threadIdx.x;
    for (int idx = o; idx < 4096; idx += 64) {
        int r = idx >> 6, c = idx & 63;
        sW[c * 65 + r] = Wc1[r * 128 + c];         // Wc1[o][h], h-part
    }
    __syncthreads();
    int n0 = blockIdx.x * NPB;
    for (int ni = 0; ni < NPB; ni++) {
        int n = n0 + ni;
        if (n >= NN) break;
        s_h[o] = g_h2[n * 64 + o];
        __syncthreads();
        float acc = 0.f;
#pragma unroll
        for (int h = 0; h < 64; h++)
            acc += sW[h * 65 + o] * s_h[h];
        g_hpT[o * NPAD + n] = acc;
        __syncthreads();
    }
}

// ---------------- task MLP + t_part, all fused ----------------
__global__ void k_task(const float* __restrict__ tf,
                       const float* __restrict__ Wt1, const float* __restrict__ bt1,
                       const float* __restrict__ Wt2, const float* __restrict__ bt2,
                       const float* __restrict__ Wc1, const float* __restrict__ bc1) {
    __shared__ float s1[64], s2[64];
    int b = blockIdx.x, o = threadIdx.x;
    float4 f = *(const float4*)(tf + (size_t)b * 4);
    float a = bt1[o] + Wt1[o * 4] * f.x + Wt1[o * 4 + 1] * f.y
                     + Wt1[o * 4 + 2] * f.z + Wt1[o * 4 + 3] * f.w;
    s1[o] = fmaxf(a, 0.f);
    __syncthreads();
    float a2 = bt2[o];
#pragma unroll 8
    for (int h = 0; h < 64; h++) a2 += Wt2[o * 64 + h] * s1[h];
    s2[o] = a2;
    __syncthreads();
    float a3 = bc1[o];
#pragma unroll 8
    for (int h = 0; h < 64; h++) a3 += Wc1[o * 128 + 64 + h] * s2[h];
    g_tp[b * 64 + o] = a3;
}

// ---------------- final: scores[b,n] = sum_h relu(hp[n,h]+tp[b,h])*w[h] + bc2 ----------------
// Block: 128 node-lanes x 32 batch rows (register tile). Grid (40, 16).
__global__ void __launch_bounds__(128) k_final(const float* __restrict__ Wc2,
                                               const float* __restrict__ bc2,
                                               float* __restrict__ out) {
    __shared__ float s_tp[32 * 64];
    __shared__ float s_w[64];
    int tid = threadIdx.x;
    int n   = blockIdx.x * 128 + tid;
    int b0  = blockIdx.y * 32;
    for (int i = tid; i < 32 * 64; i += 128) s_tp[i] = g_tp[b0 * 64 + i];
    if (tid < 64) s_w[tid] = Wc2[tid];
    __syncthreads();

    float acc[32];
#pragma unroll
    for (int b = 0; b < 32; b++) acc[b] = 0.f;

    for (int h = 0; h < 64; h++) {
        float hv = g_hpT[h * NPAD + n];            // pad region is 0; safe
        float w  = s_w[h];
#pragma unroll
        for (int b = 0; b < 32; b++)
            acc[b] = fmaf(fmaxf(hv + s_tp[b * 64 + h], 0.f), w, acc[b]);
    }

    if (n < NN) {
        float bias = bc2[0];
#pragma unroll
        for (int b = 0; b < 32; b++)
            out[(size_t)(b0 + b) * NN + n] = acc[b] + bias;
    }
}

// ---------------- launch ----------------
extern "C" void kernel_launch(void* const* d_in, const int* in_sizes, int n_in,
                              void* d_out, int out_size) {
    const float* x   = (const float*)d_in[0];
    const void*  ei  = d_in[1];
    const float* tf  = (const float*)d_in[2];
    const float* Wl1 = (const float*)d_in[3];
    const float* bl1 = (const float*)d_in[4];
    const float* Wr1 = (const float*)d_in[5];
    const float* Wl2 = (const float*)d_in[6];
    const float* bl2 = (const float*)d_in[7];
    const float* Wr2 = (const float*)d_in[8];
    const float* Wt1 = (const float*)d_in[9];
    const float* bt1 = (const float*)d_in[10];
    const float* Wt2 = (const float*)d_in[11];
    const float* bt2 = (const float*)d_in[12];
    const float* Wc1 = (const float*)d_in[13];
    const float* bc1 = (const float*)d_in[14];
    const float* Wc2 = (const float*)d_in[15];
    const float* bc2 = (const float*)d_in[16];
    float* out = (float*)d_out;

    k_zero<<<1250, 256>>>();
    k_detect<<<256, 256>>>((const unsigned int*)ei);
    k_scatter1<<<(NE + 255) / 256, 256>>>(ei, x);
    k_node1<<<(NN * HID + 255) / 256, 256>>>(x, Wl1, bl1, Wr1);
    k_scatter2<<<(NE * 32) / 256, 256>>>(ei);
    k_node2a<<<(NN + NPB - 1) / NPB, 64>>>(Wl2, bl2, Wr2);
    k_node2b<<<(NN + NPB - 1) / NPB, 64>>>(Wc1);
    k_task<<<BATCH, 64>>>(tf, Wt1, bt1, Wt2, bt2, Wc1, bc1);
    k_final<<<dim3((NN + 127) / 128, BATCH / 32), 128>>>(Wc2, bc2, out);
}

// round 2
// speedup vs baseline: 1.0113x; 1.0113x over previous
#include <cuda_runtime.h>

#define NN     5000
#define NNPAD  5120
#define NE     160000
#define HID    64
#define BATCH  512

// ---------------- scratch (device globals: allocation-free) ----------------
__device__ int   g_cnt [NN];
__device__ int   g_rowptr[NN + 1];
__device__ int   g_cur [NN];
__device__ int   g_esrc[NE];
__device__ float g_h1  [NN * HID];
__device__ float g_h2  [NN * HID];
__device__ float g_hp  [NNPAD * HID];   // h_part, row-major [n][h]
__device__ float g_tp  [BATCH * HID];
__device__ int   g_i32;

union U64 { unsigned long long u; float2 f; };

__device__ __forceinline__ unsigned long long pack2(float a, float b) {
    unsigned long long r;
    asm("mov.b64 %0, {%1, %2};" : "=l"(r) : "f"(a), "f"(b));
    return r;
}

__device__ __forceinline__ void edge_decode(const void* __restrict__ ei, int e,
                                            int& s, int& d) {
    if (g_i32) {
        const int* p = (const int*)ei;
        s = p[e]; d = p[NE + e];
    } else {
        const long long* p = (const long long*)ei;
        s = (int)p[e]; d = (int)p[NE + e];
    }
}

// ---------------- zero ----------------
__global__ void k_zero() {
    int i = blockIdx.x * blockDim.x + threadIdx.x;
    if (i == 0) g_i32 = 0;
    if (i < NN) g_cnt[i] = 0;
}

// ---------------- int32 vs int64 edge dtype detection ----------------
__global__ void k_detect(const unsigned int* __restrict__ w) {
    unsigned int acc = 0;
    for (int i = blockIdx.x * blockDim.x + threadIdx.x; i < NE; i += gridDim.x * blockDim.x)
        acc |= w[2 * i + 1];
    if (__any_sync(0xffffffffu, acc != 0) && (threadIdx.x & 31) == 0)
        atomicOr(&g_i32, 1);
}

// ---------------- CSR build: histogram ----------------
__global__ void k_hist(const void* __restrict__ ei) {
    int e = blockIdx.x * blockDim.x + threadIdx.x;
    if (e >= NE) return;
    int s, d; edge_decode(ei, e, s, d);
    atomicAdd(&g_cnt[d], 1);
}

// ---------------- CSR build: single-block scan over 5000 counts ----------------
__global__ void k_scan() {
    __shared__ int sp[1024];
    int t = threadIdx.x;
    int base = t * 5;
    int c[5]; int s = 0;
#pragma unroll
    for (int i = 0; i < 5; i++) {
        int idx = base + i;
        c[i] = (idx < NN) ? g_cnt[idx] : 0;
        s += c[i];
    }
    sp[t] = s;
    __syncthreads();
    for (int off = 1; off < 1024; off <<= 1) {
        int v = sp[t];
        int add = (t >= off) ? sp[t - off] : 0;
        __syncthreads();
        sp[t] = v + add;
        __syncthreads();
    }
    int run = sp[t] - s;   // exclusive prefix
#pragma unroll
    for (int i = 0; i < 5; i++) {
        int idx = base + i;
        if (idx <= NN) {
            g_rowptr[idx] = run;
            if (idx < NN) g_cur[idx] = run;
        }
        run += c[i];
    }
}

// ---------------- CSR build: fill src lists ----------------
__global__ void k_fill(const void* __restrict__ ei) {
    int e = blockIdx.x * blockDim.x + threadIdx.x;
    if (e >= NE) return;
    int s, d; edge_decode(ei, e, s, d);
    int pos = atomicAdd(&g_cur[d], 1);
    g_esrc[pos] = s;
}

// ---------------- layer 1: warp per node, gather mean(x) + fused matvec ----------------
__global__ void k_l1(const float* __restrict__ x,
                     const float* __restrict__ Wl1, const float* __restrict__ bl1,
                     const float* __restrict__ Wr1) {
    int gt   = blockIdx.x * blockDim.x + threadIdx.x;
    int n    = gt >> 5;
    int lane = threadIdx.x & 31;
    if (n >= NN) return;
    int start = g_rowptr[n], end = g_rowptr[n + 1];
    float4 acc = make_float4(0.f, 0.f, 0.f, 0.f);
    for (int e = start + lane; e < end; e += 32) {
        int s = g_esrc[e];
        float4 xv = *(const float4*)(x + (size_t)s * 4);
        acc.x += xv.x; acc.y += xv.y; acc.z += xv.z; acc.w += xv.w;
    }
#pragma unroll
    for (int off = 16; off; off >>= 1) {
        acc.x += __shfl_xor_sync(0xffffffffu, acc.x, off);
        acc.y += __shfl_xor_sync(0xffffffffu, acc.y, off);
        acc.z += __shfl_xor_sync(0xffffffffu, acc.z, off);
        acc.w += __shfl_xor_sync(0xffffffffu, acc.w, off);
    }
    float invd = 1.f / fmaxf((float)(end - start), 1.f);
    float m0 = acc.x * invd, m1 = acc.y * invd, m2 = acc.z * invd, m3 = acc.w * invd;
    float4 xn = *(const float4*)(x + (size_t)n * 4);
#pragma unroll
    for (int k = 0; k < 2; k++) {
        int o = lane + 32 * k;
        float a = bl1[o];
        a += Wl1[o * 4 + 0] * m0 + Wl1[o * 4 + 1] * m1
           + Wl1[o * 4 + 2] * m2 + Wl1[o * 4 + 3] * m3;
        a += Wr1[o * 4 + 0] * xn.x + Wr1[o * 4 + 1] * xn.y
           + Wr1[o * 4 + 2] * xn.z + Wr1[o * 4 + 3] * xn.w;
        g_h1[n * 64 + o] = fmaxf(a, 0.f);
    }
}

// ---------------- layer 2: CSR gather + matvec (8 groups of 64, 4 iters) ----------------
#define L2_GROUPS 8
#define L2_NPB    4
__global__ void __launch_bounds__(512) k_l2(const float* __restrict__ Wl2,
                                            const float* __restrict__ bl2,
                                            const float* __restrict__ Wr2) {
    __shared__ float sWl[64 * 65], sWr[64 * 65];
    __shared__ float s_mean[L2_GROUPS][64], s_x[L2_GROUPS][64];
    int tid = threadIdx.x;
    int g = tid >> 6, o = tid & 63;
    for (int idx = tid; idx < 4096; idx += 512) {
        int r = idx >> 6, c = idx & 63;            // r = out, c = in
        sWl[c * 65 + r] = Wl2[idx];
        sWr[c * 65 + r] = Wr2[idx];
    }
    float bias = bl2[o];
    __syncthreads();
    int n_base = blockIdx.x * (L2_GROUPS * L2_NPB) + g * L2_NPB;
    for (int ni = 0; ni < L2_NPB; ni++) {
        int n = n_base + ni;
        bool ok = (n < NN);
        if (ok) {
            int start = g_rowptr[n], end = g_rowptr[n + 1];
            float sum = 0.f;
            for (int e = start; e < end; e++) {
                int s = g_esrc[e];
                sum += g_h1[s * 64 + o];
            }
            float invd = 1.f / fmaxf((float)(end - start), 1.f);
            s_mean[g][o] = sum * invd;
            s_x[g][o]    = g_h1[n * 64 + o];
        }
        __syncthreads();
        if (ok) {
            float acc = bias;
#pragma unroll
            for (int h = 0; h < 64; h++)
                acc += sWl[h * 65 + o] * s_mean[g][h] + sWr[h * 65 + o] * s_x[g][h];
            g_h2[n * 64 + o] = fmaxf(acc, 0.f);
        }
        __syncthreads();
    }
}

// ---------------- h_part = h2 @ Wc1[:, :64]^T  (row-major output) ----------------
__global__ void k_hpart(const float* __restrict__ Wc1) {
    __shared__ float sW[64 * 65];   // [h][o]
    int tid = threadIdx.x;
    for (int idx = tid; idx < 4096; idx += 256) {
        int r = idx >> 6, c = idx & 63;            // r = out o, c = in h
        sW[c * 65 + r] = Wc1[r * 128 + c];
    }
    __syncthreads();
    int t = blockIdx.x * blockDim.x + tid;
    if (t >= NN * 64) return;
    int n = t >> 6, o = t & 63;
    const float* h2 = g_h2 + n * 64;
    float acc = 0.f;
#pragma unroll
    for (int h = 0; h < 64; h++)
        acc += sW[h * 65 + o] * h2[h];
    g_hp[t] = acc;
}

// ---------------- task MLP + t_part ----------------
__global__ void k_task(const float* __restrict__ tf,
                       const float* __restrict__ Wt1, const float* __restrict__ bt1,
                       const float* __restrict__ Wt2, const float* __restrict__ bt2,
                       const float* __restrict__ Wc1, const float* __restrict__ bc1) {
    __shared__ float s1[64], s2[64];
    int b = blockIdx.x, o = threadIdx.x;
    float4 f = *(const float4*)(tf + (size_t)b * 4);
    float a = bt1[o] + Wt1[o * 4] * f.x + Wt1[o * 4 + 1] * f.y
                     + Wt1[o * 4 + 2] * f.z + Wt1[o * 4 + 3] * f.w;
    s1[o] = fmaxf(a, 0.f);
    __syncthreads();
    float a2 = bt2[o];
#pragma unroll 8
    for (int h = 0; h < 64; h++) a2 += Wt2[o * 64 + h] * s1[h];
    s2[o] = a2;
    __syncthreads();
    float a3 = bc1[o];
#pragma unroll 8
    for (int h = 0; h < 64; h++) a3 += Wc1[o * 128 + 64 + h] * s2[h];
    g_tp[b * 64 + o] = a3;
}

// ---------------- final: scores[b,n] = sum_h relu(hp[n,h]+tp[b,h])*w[h] + bc2 ----------------
// 128 node-lanes x 32 batch rows per block; f32x2 packed math; grid (40, 16)
__global__ void __launch_bounds__(128) k_final(const float* __restrict__ Wc2,
                                               const float* __restrict__ bc2,
                                               float* __restrict__ out) {
    __shared__ float s_hp[64 * 129];                    // [h][n_local], pad 129
    __shared__ __align__(8) float s_tp[64 * 32];        // [h][b_local]
    __shared__ unsigned long long s_w2[64];
    int tid = threadIdx.x;
    int n0  = blockIdx.x * 128;
    int b0  = blockIdx.y * 32;

    // load hp tile coalesced, transpose into smem
    for (int idx = tid; idx < 128 * 64; idx += 128) {
        int nl = idx >> 6, h = idx & 63;
        s_hp[h * 129 + nl] = g_hp[(size_t)(n0 + nl) * 64 + h];
    }
    // load tp tile coalesced, transpose into smem
    for (int idx = tid; idx < 32 * 64; idx += 128) {
        int bl = idx >> 6, h = idx & 63;
        s_tp[h * 32 + bl] = g_tp[(size_t)(b0 + bl) * 64 + h];
    }
    if (tid < 64) {
        float w = Wc2[tid];
        s_w2[tid] = pack2(w, w);
    }
    __syncthreads();

    U64 acc[16];
#pragma unroll
    for (int p = 0; p < 16; p++) acc[p].u = 0ull;

    for (int h = 0; h < 64; h++) {
        float hv = s_hp[h * 129 + tid];
        unsigned long long hv2 = pack2(hv, hv);
        unsigned long long w2  = s_w2[h];
        const unsigned long long* tp = (const unsigned long long*)(s_tp + h * 32);
#pragma unroll
        for (int p = 0; p < 16; p++) {
            U64 a;
            asm("add.rn.f32x2 %0, %1, %2;" : "=l"(a.u) : "l"(tp[p]), "l"(hv2));
            a.f.x = fmaxf(a.f.x, 0.f);
            a.f.y = fmaxf(a.f.y, 0.f);
            asm("fma.rn.f32x2 %0, %1, %2, %0;" : "+l"(acc[p].u) : "l"(a.u), "l"(w2));
        }
    }

    int n = n0 + tid;
    if (n < NN) {
        float bias = bc2[0];
#pragma unroll
        for (int p = 0; p < 16; p++) {
            out[(size_t)(b0 + 2 * p    ) * NN + n] = acc[p].f.x + bias;
            out[(size_t)(b0 + 2 * p + 1) * NN + n] = acc[p].f.y + bias;
        }
    }
}

// ---------------- launch ----------------
extern "C" void kernel_launch(void* const* d_in, const int* in_sizes, int n_in,
                              void* d_out, int out_size) {
    const float* x   = (const float*)d_in[0];
    const void*  ei  = d_in[1];
    const float* tf  = (const float*)d_in[2];
    const float* Wl1 = (const float*)d_in[3];
    const float* bl1 = (const float*)d_in[4];
    const float* Wr1 = (const float*)d_in[5];
    const float* Wl2 = (const float*)d_in[6];
    const float* bl2 = (const float*)d_in[7];
    const float* Wr2 = (const float*)d_in[8];
    const float* Wt1 = (const float*)d_in[9];
    const float* bt1 = (const float*)d_in[10];
    const float* Wt2 = (const float*)d_in[11];
    const float* bt2 = (const float*)d_in[12];
    const float* Wc1 = (const float*)d_in[13];
    const float* bc1 = (const float*)d_in[14];
    const float* Wc2 = (const float*)d_in[15];
    const float* bc2 = (const float*)d_in[16];
    float* out = (float*)d_out;

    k_zero  <<<(NN + 255) / 256, 256>>>();
    k_detect<<<64, 256>>>((const unsigned int*)ei);
    k_hist  <<<(NE + 255) / 256, 256>>>(ei);
    k_scan  <<<1, 1024>>>();
    k_fill  <<<(NE + 255) / 256, 256>>>(ei);
    k_l1    <<<(NN * 32 + 255) / 256, 256>>>(x, Wl1, bl1, Wr1);
    k_l2    <<<(NN + L2_GROUPS * L2_NPB - 1) / (L2_GROUPS * L2_NPB), 512>>>(Wl2, bl2, Wr2);
    k_hpart <<<(NN * 64 + 255) / 256, 256>>>(Wc1);
    k_task  <<<BATCH, 64>>>(tf, Wt1, bt1, Wt2, bt2, Wc1, bc1);
    k_final <<<dim3((NN + 127) / 128, BATCH / 32), 128>>>(Wc2, bc2, out);
}